// round 16
// baseline (speedup 1.0000x reference)
#include <cuda_runtime.h>
#include <cstdint>
#include <math.h>

// S4D via chunked state-passing + tf32 tensor cores. R16 = R15 +
//  - param kernel v2: complex-power tables built by iterated multiplication
//    (FMA pipe) instead of per-element expf/sincosf (param was MUFU-bound:
//    ~30K MUFU per h ~= 10us of the 121.6us total)
//  - pass B Toeplitz fragment reuse: T(mt+1,kk+2)=T(mt,kk) (-6 LDG.128/warp)
//  - block->(b,h) remap so consecutive blocks share h (L2 locality)

constexpr int Hh = 256;
constexpr int N2 = 32;
constexpr int Bb = 16;
constexpr int Ll = 8192;
constexpr int LC  = 64;
constexpr int NC  = 128;
constexpr int STR = 72;     // smem row stride (8 mod 32: conflict-free LDS.64)

// fragment-format matrices: [h][mtile(4)][kk(8)][lane(32)][reg(4)]
__device__ float g_Tf[Hh * 4 * 8 * 128];
__device__ float g_Vf[Hh * 4 * 8 * 128];
__device__ float g_Pf[Hh * 4 * 8 * 128];
__device__ float g_w64r[Hh * N2];
__device__ float g_w64i[Hh * N2];

__device__ __forceinline__ float tf32r(float x) {
    uint32_t u;
    asm("cvt.rna.tf32.f32 %0, %1;" : "=r"(u) : "f"(x));
    return __uint_as_float(u);
}

__device__ __forceinline__ void mma_tf32(float* d, const uint32_t a[4],
                                         uint32_t b0, uint32_t b1) {
    asm volatile(
        "mma.sync.aligned.m16n8k8.row.col.f32.tf32.tf32.f32 "
        "{%0,%1,%2,%3}, {%4,%5,%6,%7}, {%8,%9}, {%0,%1,%2,%3};"
        : "+f"(d[0]), "+f"(d[1]), "+f"(d[2]), "+f"(d[3])
        : "r"(a[0]), "r"(a[1]), "r"(a[2]), "r"(a[3]), "r"(b0), "r"(b1));
}

__device__ __forceinline__ void csq(float ar, float ai, float& br, float& bi) {
    br = fmaf(ar, ar, -ai * ai);
    bi = 2.0f * ar * ai;
}
__device__ __forceinline__ void cmul(float& pr, float& pi, float ar, float ai) {
    const float nr = fmaf(pr, ar, -pi * ai);
    pi = fmaf(pr, ai, pi * ar);
    pr = nr;
}

// ============================ param kernel =============================
__global__ __launch_bounds__(256, 4)
void s4d_param(const float* __restrict__ log_dt,
               const float* __restrict__ log_A_real,
               const float* __restrict__ A_imag,
               const float* __restrict__ C,
               const float* __restrict__ Dv)
{
    const int h = blockIdx.x;
    const int t = threadIdx.x;

    __shared__ float pwr_s[65][33], pwi_s[65][33];   // w^e, e = 0..64
    __shared__ float k_s[64];
    __shared__ float ctr_s[N2], cti_s[N2], wr_s[N2], wi_s[N2];

    // ---- phase 1: per-mode parameters (only place MUFU is used) ----
    if (t < N2) {
        const int n = t;
        const float dt = expf(log_dt[h]);
        const float ar = -expf(log_A_real[h * N2 + n]);
        const float ai = A_imag[h * N2 + n];
        const float dtar = ar * dt, dtai = ai * dt;
        const float na = ar * ar + ai * ai;
        const float mag = expf(dtar);
        const float wr = mag * cosf(dtai);
        const float wi = mag * sinf(dtai);
        const float tr = wr - 1.0f, ti = wi;
        const float qr = (tr * ar + ti * ai) / na;
        const float qi = (ti * ar - tr * ai) / na;
        const float cr = C[(h * N2 + n) * 2 + 0];
        const float ci = C[(h * N2 + n) * 2 + 1];
        ctr_s[n] = 2.0f * (cr * qr - ci * qi);
        cti_s[n] = 2.0f * (cr * qi + ci * qr);
        wr_s[n] = wr;
        wi_s[n] = wi;
    }
    __syncthreads();

    // ---- phase 2: power table by iterated complex multiply ----
    {
        const int n   = t & 31;
        const int oct = t >> 5;          // 8 octaves of 8 powers each
        const float wr = wr_s[n], wi = wi_s[n];
        float w2r, w2i, w4r, w4i, w8r, w8i, w16r, w16i, w32r, w32i;
        csq(wr,  wi,  w2r,  w2i);
        csq(w2r, w2i, w4r,  w4i);
        csq(w4r, w4i, w8r,  w8i);
        csq(w8r, w8i, w16r, w16i);
        csq(w16r, w16i, w32r, w32i);
        float pr = 1.0f, pi = 0.0f;      // p = w^(8*oct)
        if (oct & 1) cmul(pr, pi, w8r,  w8i);
        if (oct & 2) cmul(pr, pi, w16r, w16i);
        if (oct & 4) cmul(pr, pi, w32r, w32i);
        #pragma unroll
        for (int e2 = 0; e2 < 8; ++e2) {
            pwr_s[8 * oct + e2][n] = pr;
            pwi_s[8 * oct + e2][n] = pi;
            cmul(pr, pi, wr, wi);
        }
        if (oct == 7) {                  // e = 64 (for PM i=63 and w64)
            pwr_s[64][n] = pr;
            pwi_s[64][n] = pi;
        }
    }
    __syncthreads();

    // ---- phase 3: k[m] and w^64 ----
    if (t < 64) {
        float sum = 0.0f;
        for (int n = 0; n < N2; ++n)
            sum += ctr_s[n] * pwr_s[t][n] - cti_s[n] * pwi_s[t][n];
        k_s[t] = sum;
    }
    if (t < N2) {
        g_w64r[h * N2 + t] = pwr_s[64][t];
        g_w64i[h * N2 + t] = pwi_s[64][t];
    }
    __syncthreads();

    // ---- phase 4: fragment-format writes ----
    const int warp = t >> 5;
    const int lane = t & 31;
    const int gid  = lane >> 2;
    const int tig  = lane & 3;
    const int mt   = warp & 3;
    const int kk0  = (warp >> 2) * 4;    // 4 kks per warp
    const int r0   = 16 * mt + gid;
    const float k0pD = k_s[0] + Dv[h];

    auto Tval = [&](int r, int c) -> float {
        if (c > r) return 0.0f;
        if (c == r) return tf32r(k0pD);
        return tf32r(k_s[r - c]);
    };
    auto Vval = [&](int r, int c) -> float {
        const int n = r & 31;
        const int e = 63 - c;
        return tf32r((r < 32) ? pwr_s[e][n] : pwi_s[e][n]);
    };
    auto Pval = [&](int r, int c) -> float {
        const int n = c & 31;
        const int e = r + 1;
        const float zr = ctr_s[n] * pwr_s[e][n] - cti_s[n] * pwi_s[e][n];
        const float zi = ctr_s[n] * pwi_s[e][n] + cti_s[n] * pwr_s[e][n];
        return tf32r((c < 32) ? zr : -zi);
    };

    for (int kk = kk0; kk < kk0 + 4; ++kk) {
        const int c0 = kk * 8 + tig;
        const int idx = ((h * 4 + mt) * 8 + kk) * 32 + lane;
        float4 v;
        v.x = Tval(r0, c0);     v.y = Tval(r0 + 8, c0);
        v.z = Tval(r0, c0 + 4); v.w = Tval(r0 + 8, c0 + 4);
        reinterpret_cast<float4*>(g_Tf)[idx] = v;
        v.x = Vval(r0, c0);     v.y = Vval(r0 + 8, c0);
        v.z = Vval(r0, c0 + 4); v.w = Vval(r0 + 8, c0 + 4);
        reinterpret_cast<float4*>(g_Vf)[idx] = v;
        v.x = Pval(r0, c0);     v.y = Pval(r0 + 8, c0);
        v.z = Pval(r0, c0 + 4); v.w = Pval(r0 + 8, c0 + 4);
        reinterpret_cast<float4*>(g_Pf)[idx] = v;
    }
}

// ============================= main kernel =============================
__global__ __launch_bounds__(256, 3)
void s4d_main(const float* __restrict__ u, float* __restrict__ y)
{
    extern __shared__ float sh[];
    float* u_s   = sh;                    // [NC][STR] u, tf32, k-permuted
    float* vx_s  = sh + NC * STR;         // [NC][STR] V then X, k-permuted
    float* seg_s = sh + 2 * NC * STR;     // [8][68] segment totals (r, i)

    const int z = blockIdx.x;
    const int h = z >> 4;                 // consecutive blocks share h
    const int b = z & 15;
    const int g = b * Hh + h;             // sequence index b*H + h
    const int tid   = threadIdx.x;
    const int warp  = tid >> 5;
    const int lane  = tid & 31;
    const int gid   = lane >> 2;
    const int tig   = lane & 3;
    const int mrow2 = warp >> 2;          // 0..1 : which M half (2 mtiles)
    const int nq    = warp & 3;           // 0..3 : which 32-chunk quarter

    const float* __restrict__ up = u + (size_t)g * Ll;
    float*       __restrict__ yp = y + (size_t)g * Ll;

    // ---- stage u: tf32-round + k-permute (within each 8: i->2(i&3)|(i>>2))
    {
        const float4* up4 = reinterpret_cast<const float4*>(up);
        for (int gi = tid; gi < Ll / 8; gi += 256) {
            const int c = gi >> 3, grp = gi & 7;
            const float4 a = up4[gi * 2];
            const float4 bq = up4[gi * 2 + 1];
            float4 w0, w1;
            w0.x = tf32r(a.x); w0.y = tf32r(bq.x);
            w0.z = tf32r(a.y); w0.w = tf32r(bq.y);
            w1.x = tf32r(a.z); w1.y = tf32r(bq.z);
            w1.z = tf32r(a.w); w1.w = tf32r(bq.w);
            float* dst = &u_s[c * STR + grp * 8];
            reinterpret_cast<float4*>(dst)[0] = w0;
            reinterpret_cast<float4*>(dst)[1] = w1;
        }
    }
    __syncthreads();

    // ================== pass A: V = VM @ U ===============================
    {
        float accV[2][4][4] = {};
        const float4* Vf4 = reinterpret_cast<const float4*>(g_Vf);

        #pragma unroll
        for (int kk = 0; kk < 8; ++kk) {
            uint32_t aV2[2][4];
            #pragma unroll
            for (int mt2 = 0; mt2 < 2; ++mt2) {
                const int mt = mrow2 * 2 + mt2;
                const float4 v = Vf4[((h * 4 + mt) * 8 + kk) * 32 + lane];
                aV2[mt2][0] = __float_as_uint(v.x);
                aV2[mt2][1] = __float_as_uint(v.y);
                aV2[mt2][2] = __float_as_uint(v.z);
                aV2[mt2][3] = __float_as_uint(v.w);
            }
            #pragma unroll
            for (int nt = 0; nt < 4; ++nt) {
                const int nb = nq * 32 + nt * 8;
                const float2 bb = *reinterpret_cast<const float2*>(
                    &u_s[(nb + gid) * STR + kk * 8 + 2 * tig]);
                const uint32_t b0 = __float_as_uint(bb.x);
                const uint32_t b1 = __float_as_uint(bb.y);
                mma_tf32(accV[0][nt], aV2[0], b0, b1);
                mma_tf32(accV[1][nt], aV2[1], b0, b1);
            }
        }
        // store V
        #pragma unroll
        for (int nt = 0; nt < 4; ++nt) {
            const int cc = nq * 32 + nt * 8 + 2 * tig;
            #pragma unroll
            for (int mt2 = 0; mt2 < 2; ++mt2) {
                const int mb = 16 * (mrow2 * 2 + mt2);
                const int p0 = mb + ((gid & 3) << 1) + (gid >> 2);
                vx_s[cc * STR + p0]           = accV[mt2][nt][0];
                vx_s[(cc + 1) * STR + p0]     = accV[mt2][nt][1];
                vx_s[cc * STR + p0 + 8]       = accV[mt2][nt][2];
                vx_s[(cc + 1) * STR + p0 + 8] = accV[mt2][nt][3];
            }
        }
    }
    __syncthreads();

    // ========== scan: local pre-states in registers, totals to smem ======
    const float w64r = g_w64r[h * N2 + lane];
    const float w64i = g_w64i[h * N2 + lane];
    const int pl = (lane & 24) | ((lane & 3) << 1) | ((lane >> 2) & 1);
    const int sb = warp * 16;
    float sxr[16], sxi[16];
    {
        float xr = 0.0f, xi = 0.0f;
        #pragma unroll
        for (int cc = 0; cc < 16; ++cc) {
            const int c = sb + cc;
            const float vr = vx_s[c * STR + pl];
            const float vi = vx_s[c * STR + 32 + pl];
            sxr[cc] = xr;
            sxi[cc] = xi;
            const float nxr = fmaf(w64r, xr, fmaf(-w64i, xi, vr));
            xi = fmaf(w64i, xr, fmaf(w64r, xi, vi));
            xr = nxr;
        }
        seg_s[warp * 68 + lane]      = xr;
        seg_s[warp * 68 + 32 + lane] = xi;
    }
    __syncthreads();

    // ==== every warp computes its own prefix (parallel, <=7-term chain) ==
    float pr = 0.0f, pi = 0.0f;
    {
        float qr = w64r, qi = w64i;                   // q = w64^16
        #pragma unroll
        for (int s2 = 0; s2 < 4; ++s2) {
            const float nr = qr * qr - qi * qi;
            qi = 2.0f * qr * qi;
            qr = nr;
        }
        for (int w = 0; w < warp; ++w) {
            const float tr2 = seg_s[w * 68 + lane];
            const float ti2 = seg_s[w * 68 + 32 + lane];
            const float nr = fmaf(qr, pr, fmaf(-qi, pi, tr2));
            pi = fmaf(qi, pr, fmaf(qr, pi, ti2));
            pr = nr;
        }
    }

    // ==== correction: X[c] = tf32r(local_prestate + prefix) ==============
    {
        #pragma unroll
        for (int cc = 0; cc < 16; ++cc) {
            const int c = sb + cc;
            vx_s[c * STR + pl]      = tf32r(sxr[cc] + pr);
            vx_s[c * STR + 32 + pl] = tf32r(sxi[cc] + pi);
            const float nr = pr * w64r - pi * w64i;
            pi = fmaf(pr, w64i, pi * w64r);
            pr = nr;
        }
    }
    __syncthreads();

    // ====== pass B: Y = T @ U + PM @ X (fused kk loop), then store =======
    {
        float accY[2][4][4] = {};
        const float4* Tf4 = reinterpret_cast<const float4*>(g_Tf);
        const float4* Pf4 = reinterpret_cast<const float4*>(g_Pf);
        uint32_t troll[2][4];          // T(mt0+1, kk+2) == T(mt0, kk)

        #pragma unroll
        for (int kk = 0; kk < 8; ++kk) {
            uint32_t aT2[2][4], aP2[2][4];
            {
                const int mt0 = mrow2 * 2;
                const float4 w = Tf4[((h * 4 + mt0) * 8 + kk) * 32 + lane];
                aT2[0][0] = __float_as_uint(w.x);
                aT2[0][1] = __float_as_uint(w.y);
                aT2[0][2] = __float_as_uint(w.z);
                aT2[0][3] = __float_as_uint(w.w);
                if (kk < 2) {
                    const float4 w1 = Tf4[((h * 4 + mt0 + 1) * 8 + kk) * 32 + lane];
                    aT2[1][0] = __float_as_uint(w1.x);
                    aT2[1][1] = __float_as_uint(w1.y);
                    aT2[1][2] = __float_as_uint(w1.z);
                    aT2[1][3] = __float_as_uint(w1.w);
                } else {
                    aT2[1][0] = troll[kk & 1][0];
                    aT2[1][1] = troll[kk & 1][1];
                    aT2[1][2] = troll[kk & 1][2];
                    aT2[1][3] = troll[kk & 1][3];
                }
                troll[kk & 1][0] = aT2[0][0];
                troll[kk & 1][1] = aT2[0][1];
                troll[kk & 1][2] = aT2[0][2];
                troll[kk & 1][3] = aT2[0][3];
            }
            #pragma unroll
            for (int mt2 = 0; mt2 < 2; ++mt2) {
                const int mt = mrow2 * 2 + mt2;
                const float4 v = Pf4[((h * 4 + mt) * 8 + kk) * 32 + lane];
                aP2[mt2][0] = __float_as_uint(v.x);
                aP2[mt2][1] = __float_as_uint(v.y);
                aP2[mt2][2] = __float_as_uint(v.z);
                aP2[mt2][3] = __float_as_uint(v.w);
            }
            #pragma unroll
            for (int nt = 0; nt < 4; ++nt) {
                const int nb = nq * 32 + nt * 8;
                const float2 bu = *reinterpret_cast<const float2*>(
                    &u_s[(nb + gid) * STR + kk * 8 + 2 * tig]);
                const float2 bx = *reinterpret_cast<const float2*>(
                    &vx_s[(nb + gid) * STR + kk * 8 + 2 * tig]);
                const uint32_t u0 = __float_as_uint(bu.x);
                const uint32_t u1 = __float_as_uint(bu.y);
                const uint32_t x0 = __float_as_uint(bx.x);
                const uint32_t x1 = __float_as_uint(bx.y);
                mma_tf32(accY[0][nt], aT2[0], u0, u1);
                mma_tf32(accY[1][nt], aT2[1], u0, u1);
                mma_tf32(accY[0][nt], aP2[0], x0, x1);
                mma_tf32(accY[1][nt], aP2[1], x0, x1);
            }
        }
        #pragma unroll
        for (int mt2 = 0; mt2 < 2; ++mt2) {
            const int r0 = 16 * (mrow2 * 2 + mt2) + gid;
            #pragma unroll
            for (int nt = 0; nt < 4; ++nt) {
                const int cc = nq * 32 + nt * 8 + 2 * tig;
                yp[cc * LC + r0]           = accY[mt2][nt][0];
                yp[(cc + 1) * LC + r0]     = accY[mt2][nt][1];
                yp[cc * LC + r0 + 8]       = accY[mt2][nt][2];
                yp[(cc + 1) * LC + r0 + 8] = accY[mt2][nt][3];
            }
        }
    }
}

// ============================== launch =================================
extern "C" void kernel_launch(void* const* d_in, const int* in_sizes, int n_in,
                              void* d_out, int out_size)
{
    const float* u          = (const float*)d_in[0];
    const float* log_dt     = (const float*)d_in[1];
    const float* log_A_real = (const float*)d_in[2];
    const float* A_imag     = (const float*)d_in[3];
    const float* C          = (const float*)d_in[4];
    const float* D          = (const float*)d_in[5];
    float* y = (float*)d_out;

    const int smem = (2 * NC * STR + 8 * 68) * (int)sizeof(float); // 75904 B
    cudaFuncSetAttribute(s4d_main,
                         cudaFuncAttributeMaxDynamicSharedMemorySize, smem);

    s4d_param<<<Hh, 256>>>(log_dt, log_A_real, A_imag, C, D);
    s4d_main<<<Bb * Hh, 256, smem>>>(u, y);
}

// round 17
// speedup vs baseline: 1.0529x; 1.0529x over previous
#include <cuda_runtime.h>
#include <cstdint>
#include <math.h>

// S4D via chunked state-passing + tf32 tensor cores. R17 = R15 main kernel
// (verbatim — the R16 troll-buffer and block-remap changes regressed main
// 111.7->118.6us and are reverted) + R16's param kernel v2 (power tables by
// iterated complex multiply instead of expf/sincosf; param ~10us -> ~4us).

constexpr int Hh = 256;
constexpr int N2 = 32;
constexpr int Bb = 16;
constexpr int Ll = 8192;
constexpr int LC  = 64;
constexpr int NC  = 128;
constexpr int STR = 72;     // smem row stride (8 mod 32: conflict-free LDS.64)

// fragment-format matrices: [h][mtile(4)][kk(8)][lane(32)][reg(4)]
__device__ float g_Tf[Hh * 4 * 8 * 128];
__device__ float g_Vf[Hh * 4 * 8 * 128];
__device__ float g_Pf[Hh * 4 * 8 * 128];
__device__ float g_w64r[Hh * N2];
__device__ float g_w64i[Hh * N2];

__device__ __forceinline__ float tf32r(float x) {
    uint32_t u;
    asm("cvt.rna.tf32.f32 %0, %1;" : "=r"(u) : "f"(x));
    return __uint_as_float(u);
}

__device__ __forceinline__ void mma_tf32(float* d, const uint32_t a[4],
                                         uint32_t b0, uint32_t b1) {
    asm volatile(
        "mma.sync.aligned.m16n8k8.row.col.f32.tf32.tf32.f32 "
        "{%0,%1,%2,%3}, {%4,%5,%6,%7}, {%8,%9}, {%0,%1,%2,%3};"
        : "+f"(d[0]), "+f"(d[1]), "+f"(d[2]), "+f"(d[3])
        : "r"(a[0]), "r"(a[1]), "r"(a[2]), "r"(a[3]), "r"(b0), "r"(b1));
}

__device__ __forceinline__ void csq(float ar, float ai, float& br, float& bi) {
    br = fmaf(ar, ar, -ai * ai);
    bi = 2.0f * ar * ai;
}
__device__ __forceinline__ void cmul(float& pr, float& pi, float ar, float ai) {
    const float nr = fmaf(pr, ar, -pi * ai);
    pi = fmaf(pr, ai, pi * ar);
    pr = nr;
}

// ============================ param kernel =============================
__global__ __launch_bounds__(256, 4)
void s4d_param(const float* __restrict__ log_dt,
               const float* __restrict__ log_A_real,
               const float* __restrict__ A_imag,
               const float* __restrict__ C,
               const float* __restrict__ Dv)
{
    const int h = blockIdx.x;
    const int t = threadIdx.x;

    __shared__ float pwr_s[65][33], pwi_s[65][33];   // w^e, e = 0..64
    __shared__ float k_s[64];
    __shared__ float ctr_s[N2], cti_s[N2], wr_s[N2], wi_s[N2];

    // ---- phase 1: per-mode parameters (only place MUFU is used) ----
    if (t < N2) {
        const int n = t;
        const float dt = expf(log_dt[h]);
        const float ar = -expf(log_A_real[h * N2 + n]);
        const float ai = A_imag[h * N2 + n];
        const float dtar = ar * dt, dtai = ai * dt;
        const float na = ar * ar + ai * ai;
        const float mag = expf(dtar);
        const float wr = mag * cosf(dtai);
        const float wi = mag * sinf(dtai);
        const float tr = wr - 1.0f, ti = wi;
        const float qr = (tr * ar + ti * ai) / na;
        const float qi = (ti * ar - tr * ai) / na;
        const float cr = C[(h * N2 + n) * 2 + 0];
        const float ci = C[(h * N2 + n) * 2 + 1];
        ctr_s[n] = 2.0f * (cr * qr - ci * qi);
        cti_s[n] = 2.0f * (cr * qi + ci * qr);
        wr_s[n] = wr;
        wi_s[n] = wi;
    }
    __syncthreads();

    // ---- phase 2: power table by iterated complex multiply ----
    {
        const int n   = t & 31;
        const int oct = t >> 5;          // 8 octaves of 8 powers each
        const float wr = wr_s[n], wi = wi_s[n];
        float w2r, w2i, w4r, w4i, w8r, w8i, w16r, w16i, w32r, w32i;
        csq(wr,  wi,  w2r,  w2i);
        csq(w2r, w2i, w4r,  w4i);
        csq(w4r, w4i, w8r,  w8i);
        csq(w8r, w8i, w16r, w16i);
        csq(w16r, w16i, w32r, w32i);
        float pr = 1.0f, pi = 0.0f;      // p = w^(8*oct)
        if (oct & 1) cmul(pr, pi, w8r,  w8i);
        if (oct & 2) cmul(pr, pi, w16r, w16i);
        if (oct & 4) cmul(pr, pi, w32r, w32i);
        #pragma unroll
        for (int e2 = 0; e2 < 8; ++e2) {
            pwr_s[8 * oct + e2][n] = pr;
            pwi_s[8 * oct + e2][n] = pi;
            cmul(pr, pi, wr, wi);
        }
        if (oct == 7) {                  // e = 64 (for PM i=63 and w64)
            pwr_s[64][n] = pr;
            pwi_s[64][n] = pi;
        }
    }
    __syncthreads();

    // ---- phase 3: k[m] and w^64 ----
    if (t < 64) {
        float sum = 0.0f;
        for (int n = 0; n < N2; ++n)
            sum += ctr_s[n] * pwr_s[t][n] - cti_s[n] * pwi_s[t][n];
        k_s[t] = sum;
    }
    if (t < N2) {
        g_w64r[h * N2 + t] = pwr_s[64][t];
        g_w64i[h * N2 + t] = pwi_s[64][t];
    }
    __syncthreads();

    // ---- phase 4: fragment-format writes ----
    const int warp = t >> 5;
    const int lane = t & 31;
    const int gid  = lane >> 2;
    const int tig  = lane & 3;
    const int mt   = warp & 3;
    const int kk0  = (warp >> 2) * 4;    // 4 kks per warp
    const int r0   = 16 * mt + gid;
    const float k0pD = k_s[0] + Dv[h];

    auto Tval = [&](int r, int c) -> float {
        if (c > r) return 0.0f;
        if (c == r) return tf32r(k0pD);
        return tf32r(k_s[r - c]);
    };
    auto Vval = [&](int r, int c) -> float {
        const int n = r & 31;
        const int e = 63 - c;
        return tf32r((r < 32) ? pwr_s[e][n] : pwi_s[e][n]);
    };
    auto Pval = [&](int r, int c) -> float {
        const int n = c & 31;
        const int e = r + 1;
        const float zr = ctr_s[n] * pwr_s[e][n] - cti_s[n] * pwi_s[e][n];
        const float zi = ctr_s[n] * pwi_s[e][n] + cti_s[n] * pwr_s[e][n];
        return tf32r((c < 32) ? zr : -zi);
    };

    for (int kk = kk0; kk < kk0 + 4; ++kk) {
        const int c0 = kk * 8 + tig;
        const int idx = ((h * 4 + mt) * 8 + kk) * 32 + lane;
        float4 v;
        v.x = Tval(r0, c0);     v.y = Tval(r0 + 8, c0);
        v.z = Tval(r0, c0 + 4); v.w = Tval(r0 + 8, c0 + 4);
        reinterpret_cast<float4*>(g_Tf)[idx] = v;
        v.x = Vval(r0, c0);     v.y = Vval(r0 + 8, c0);
        v.z = Vval(r0, c0 + 4); v.w = Vval(r0 + 8, c0 + 4);
        reinterpret_cast<float4*>(g_Vf)[idx] = v;
        v.x = Pval(r0, c0);     v.y = Pval(r0 + 8, c0);
        v.z = Pval(r0, c0 + 4); v.w = Pval(r0 + 8, c0 + 4);
        reinterpret_cast<float4*>(g_Pf)[idx] = v;
    }
}

// ============================= main kernel =============================
__global__ __launch_bounds__(256, 3)
void s4d_main(const float* __restrict__ u, float* __restrict__ y)
{
    extern __shared__ float sh[];
    float* u_s   = sh;                    // [NC][STR] u, tf32, k-permuted
    float* vx_s  = sh + NC * STR;         // [NC][STR] V then X, k-permuted
    float* seg_s = sh + 2 * NC * STR;     // [8][68] segment totals (r, i)

    const int g = blockIdx.x;             // b*H + h
    const int h = g & (Hh - 1);
    const int tid   = threadIdx.x;
    const int warp  = tid >> 5;
    const int lane  = tid & 31;
    const int gid   = lane >> 2;
    const int tig   = lane & 3;
    const int mrow2 = warp >> 2;          // 0..1 : which M half (2 mtiles)
    const int nq    = warp & 3;           // 0..3 : which 32-chunk quarter

    const float* __restrict__ up = u + (size_t)g * Ll;
    float*       __restrict__ yp = y + (size_t)g * Ll;

    // ---- stage u: tf32-round + k-permute (within each 8: i->2(i&3)|(i>>2))
    {
        const float4* up4 = reinterpret_cast<const float4*>(up);
        for (int gi = tid; gi < Ll / 8; gi += 256) {
            const int c = gi >> 3, grp = gi & 7;
            const float4 a = up4[gi * 2];
            const float4 b = up4[gi * 2 + 1];
            float4 w0, w1;
            w0.x = tf32r(a.x); w0.y = tf32r(b.x);
            w0.z = tf32r(a.y); w0.w = tf32r(b.y);
            w1.x = tf32r(a.z); w1.y = tf32r(b.z);
            w1.z = tf32r(a.w); w1.w = tf32r(b.w);
            float* dst = &u_s[c * STR + grp * 8];
            reinterpret_cast<float4*>(dst)[0] = w0;
            reinterpret_cast<float4*>(dst)[1] = w1;
        }
    }
    __syncthreads();

    // ================== pass A: V = VM @ U ===============================
    {
        float accV[2][4][4] = {};
        const float4* Vf4 = reinterpret_cast<const float4*>(g_Vf);

        #pragma unroll
        for (int kk = 0; kk < 8; ++kk) {
            uint32_t aV2[2][4];
            #pragma unroll
            for (int mt2 = 0; mt2 < 2; ++mt2) {
                const int mt = mrow2 * 2 + mt2;
                const float4 v = Vf4[((h * 4 + mt) * 8 + kk) * 32 + lane];
                aV2[mt2][0] = __float_as_uint(v.x);
                aV2[mt2][1] = __float_as_uint(v.y);
                aV2[mt2][2] = __float_as_uint(v.z);
                aV2[mt2][3] = __float_as_uint(v.w);
            }
            #pragma unroll
            for (int nt = 0; nt < 4; ++nt) {
                const int nb = nq * 32 + nt * 8;
                const float2 bb = *reinterpret_cast<const float2*>(
                    &u_s[(nb + gid) * STR + kk * 8 + 2 * tig]);
                const uint32_t b0 = __float_as_uint(bb.x);
                const uint32_t b1 = __float_as_uint(bb.y);
                mma_tf32(accV[0][nt], aV2[0], b0, b1);
                mma_tf32(accV[1][nt], aV2[1], b0, b1);
            }
        }
        // store V
        #pragma unroll
        for (int nt = 0; nt < 4; ++nt) {
            const int cc = nq * 32 + nt * 8 + 2 * tig;
            #pragma unroll
            for (int mt2 = 0; mt2 < 2; ++mt2) {
                const int mb = 16 * (mrow2 * 2 + mt2);
                const int p0 = mb + ((gid & 3) << 1) + (gid >> 2);
                vx_s[cc * STR + p0]           = accV[mt2][nt][0];
                vx_s[(cc + 1) * STR + p0]     = accV[mt2][nt][1];
                vx_s[cc * STR + p0 + 8]       = accV[mt2][nt][2];
                vx_s[(cc + 1) * STR + p0 + 8] = accV[mt2][nt][3];
            }
        }
    }
    __syncthreads();

    // ========== scan: local pre-states in registers, totals to smem ======
    const float w64r = g_w64r[h * N2 + lane];
    const float w64i = g_w64i[h * N2 + lane];
    const int pl = (lane & 24) | ((lane & 3) << 1) | ((lane >> 2) & 1);
    const int sb = warp * 16;
    float sxr[16], sxi[16];
    {
        float xr = 0.0f, xi = 0.0f;
        #pragma unroll
        for (int cc = 0; cc < 16; ++cc) {
            const int c = sb + cc;
            const float vr = vx_s[c * STR + pl];
            const float vi = vx_s[c * STR + 32 + pl];
            sxr[cc] = xr;
            sxi[cc] = xi;
            const float nxr = fmaf(w64r, xr, fmaf(-w64i, xi, vr));
            xi = fmaf(w64i, xr, fmaf(w64r, xi, vi));
            xr = nxr;
        }
        seg_s[warp * 68 + lane]      = xr;
        seg_s[warp * 68 + 32 + lane] = xi;
    }
    __syncthreads();

    // ==== every warp computes its own prefix (parallel, <=7-term chain) ==
    float pr = 0.0f, pi = 0.0f;
    {
        float qr = w64r, qi = w64i;                   // q = w64^16
        #pragma unroll
        for (int s2 = 0; s2 < 4; ++s2) {
            const float nr = qr * qr - qi * qi;
            qi = 2.0f * qr * qi;
            qr = nr;
        }
        for (int w = 0; w < warp; ++w) {
            const float tr2 = seg_s[w * 68 + lane];
            const float ti2 = seg_s[w * 68 + 32 + lane];
            const float nr = fmaf(qr, pr, fmaf(-qi, pi, tr2));
            pi = fmaf(qi, pr, fmaf(qr, pi, ti2));
            pr = nr;
        }
    }

    // ==== correction: X[c] = tf32r(local_prestate + prefix) ==============
    {
        #pragma unroll
        for (int cc = 0; cc < 16; ++cc) {
            const int c = sb + cc;
            vx_s[c * STR + pl]      = tf32r(sxr[cc] + pr);
            vx_s[c * STR + 32 + pl] = tf32r(sxi[cc] + pi);
            const float nr = pr * w64r - pi * w64i;
            pi = fmaf(pr, w64i, pi * w64r);
            pr = nr;
        }
    }
    __syncthreads();

    // ====== pass B: Y = T @ U + PM @ X (fused kk loop), then store =======
    {
        float accY[2][4][4] = {};
        const float4* Tf4 = reinterpret_cast<const float4*>(g_Tf);
        const float4* Pf4 = reinterpret_cast<const float4*>(g_Pf);

        #pragma unroll
        for (int kk = 0; kk < 8; ++kk) {
            uint32_t aT2[2][4], aP2[2][4];
            #pragma unroll
            for (int mt2 = 0; mt2 < 2; ++mt2) {
                const int mt = mrow2 * 2 + mt2;
                const float4 w = Tf4[((h * 4 + mt) * 8 + kk) * 32 + lane];
                aT2[mt2][0] = __float_as_uint(w.x);
                aT2[mt2][1] = __float_as_uint(w.y);
                aT2[mt2][2] = __float_as_uint(w.z);
                aT2[mt2][3] = __float_as_uint(w.w);
                const float4 v = Pf4[((h * 4 + mt) * 8 + kk) * 32 + lane];
                aP2[mt2][0] = __float_as_uint(v.x);
                aP2[mt2][1] = __float_as_uint(v.y);
                aP2[mt2][2] = __float_as_uint(v.z);
                aP2[mt2][3] = __float_as_uint(v.w);
            }
            #pragma unroll
            for (int nt = 0; nt < 4; ++nt) {
                const int nb = nq * 32 + nt * 8;
                const float2 bu = *reinterpret_cast<const float2*>(
                    &u_s[(nb + gid) * STR + kk * 8 + 2 * tig]);
                const float2 bx = *reinterpret_cast<const float2*>(
                    &vx_s[(nb + gid) * STR + kk * 8 + 2 * tig]);
                const uint32_t u0 = __float_as_uint(bu.x);
                const uint32_t u1 = __float_as_uint(bu.y);
                const uint32_t x0 = __float_as_uint(bx.x);
                const uint32_t x1 = __float_as_uint(bx.y);
                mma_tf32(accY[0][nt], aT2[0], u0, u1);
                mma_tf32(accY[1][nt], aT2[1], u0, u1);
                mma_tf32(accY[0][nt], aP2[0], x0, x1);
                mma_tf32(accY[1][nt], aP2[1], x0, x1);
            }
        }
        #pragma unroll
        for (int mt2 = 0; mt2 < 2; ++mt2) {
            const int r0 = 16 * (mrow2 * 2 + mt2) + gid;
            #pragma unroll
            for (int nt = 0; nt < 4; ++nt) {
                const int cc = nq * 32 + nt * 8 + 2 * tig;
                yp[cc * LC + r0]           = accY[mt2][nt][0];
                yp[(cc + 1) * LC + r0]     = accY[mt2][nt][1];
                yp[cc * LC + r0 + 8]       = accY[mt2][nt][2];
                yp[(cc + 1) * LC + r0 + 8] = accY[mt2][nt][3];
            }
        }
    }
}

// ============================== launch =================================
extern "C" void kernel_launch(void* const* d_in, const int* in_sizes, int n_in,
                              void* d_out, int out_size)
{
    const float* u          = (const float*)d_in[0];
    const float* log_dt     = (const float*)d_in[1];
    const float* log_A_real = (const float*)d_in[2];
    const float* A_imag     = (const float*)d_in[3];
    const float* C          = (const float*)d_in[4];
    const float* D          = (const float*)d_in[5];
    float* y = (float*)d_out;

    const int smem = (2 * NC * STR + 8 * 68) * (int)sizeof(float); // 75904 B
    cudaFuncSetAttribute(s4d_main,
                         cudaFuncAttributeMaxDynamicSharedMemorySize, smem);

    s4d_param<<<Hh, 256>>>(log_dt, log_A_real, A_imag, C, D);
    s4d_main<<<Bb * Hh, 256, smem>>>(u, y);
}